// round 8
// baseline (speedup 1.0000x reference)
#include <cuda_runtime.h>

// Problem dims
#define NNODES 207
#define LT     12
#define CIN    32
#define COUT   32
#define BATCH  256
#define NPAIR  (BATCH*COUT)        // 8192 (n,o) pairs
#define COLSF  (NNODES*LT)         // 2484 floats per (n,c) slice
#define PCOLS  (COLSF/2)           // 1242 float2 per slice
#define XELEMS (BATCH*CIN*COLSF)   // 20,348,928
#define NSQ    (NNODES*NNODES)

typedef unsigned long long u64;
typedef unsigned int u32;

// Scratch (static device globals — no allocation).
__device__ float g_mats[3*NSQ];    // [0]=A, [1]=A2, [2]=M
__device__ float g_Y[XELEMS];      // channel-mixed intermediate, [n][o][w][l]

// ---- packed fp32x2 helpers ---------------------------------------------
__device__ __forceinline__ u64 pack2(float x) {
    u64 r; asm("mov.b64 %0, {%1, %1};" : "=l"(r) : "f"(x)); return r;
}
__device__ __forceinline__ void ffma2(u64 &d, u64 a, u64 b) {
    asm("fma.rn.f32x2 %0, %1, %2, %0;" : "+l"(d) : "l"(a), "l"(b));
}
__device__ __forceinline__ u64 add2(u64 a, u64 b) {
    u64 r; asm("add.rn.f32x2 %0, %1, %2;" : "=l"(r) : "l"(a), "l"(b)); return r;
}

// ---- K0a: row-normalized A = (adj + I) / rowsum ------------------------
__global__ void k_norm(const float* __restrict__ adj) {
    int v = blockIdx.x;
    __shared__ float red[256];
    float s = 0.f;
    for (int w = threadIdx.x; w < NNODES; w += 256)
        s += adj[v*NNODES + w] + (w == v ? 1.f : 0.f);
    red[threadIdx.x] = s;
    __syncthreads();
    for (int st = 128; st > 0; st >>= 1) {
        if (threadIdx.x < st) red[threadIdx.x] += red[threadIdx.x + st];
        __syncthreads();
    }
    float inv = 1.f / red[0];
    for (int w = threadIdx.x; w < NNODES; w += 256)
        g_mats[v*NNODES + w] = (adj[v*NNODES + w] + (w == v ? 1.f : 0.f)) * inv;
}

// ---- K0b: A2 = A @ A ---------------------------------------------------
__global__ void k_A2() {
    int v = blockIdx.x, u = threadIdx.x;
    if (u >= NNODES) return;
    const float* A = g_mats;
    float acc = 0.f;
    for (int w = 0; w < NNODES; w++)
        acc += A[v*NNODES + w] * A[w*NNODES + u];
    g_mats[NSQ + v*NNODES + u] = acc;
}

// ---- K0c: M = AL*I + c1*A + c2*A2 + c3*(A2@A) --------------------------
__global__ void k_M() {
    const float AL = 0.05f, BE = 0.95f;
    const float c1 = AL*BE, c2 = AL*BE*BE, c3 = BE*BE*BE;
    int v = blockIdx.x, u = threadIdx.x;
    if (u >= NNODES) return;
    const float* A  = g_mats;
    const float* A2 = g_mats + NSQ;
    float acc = 0.f;
    for (int w = 0; w < NNODES; w++)
        acc += A2[v*NNODES + w] * A[w*NNODES + u];
    float r = c3*acc + c2*A2[v*NNODES + u] + c1*A[v*NNODES + u]
            + (u == v ? AL : 0.f);
    g_mats[2*NSQ + v*NNODES + u] = r;
}

// ---- K1: channel mix  Y[n,o,w,l] = sum_c W[o,c] x[n,c,w,l] -------------
// x staged to smem ONCE per block; 4 o-groups read it via conflict-free
// LDS (kills the 4x L1tex re-read that bound R6's version).
#define PCB 64   // packed columns per block
__global__ __launch_bounds__(256) void k_cmix(const float* __restrict__ x,
                                              const float* __restrict__ W) {
    __shared__ u64 Ws2[CIN][COUT];   // 8 KB: [c][o], duplicated halves
    __shared__ u64 Xs [CIN][PCB];    // 16 KB
    int n   = blockIdx.y;
    int t   = threadIdx.x;
    int pc0 = blockIdx.x * PCB;

    for (int i = t; i < CIN*COUT; i += 256) {
        int o = i >> 5, c = i & 31;
        Ws2[c][o] = pack2(W[i]);     // W layout (COUT, CIN)
    }
    const u64* xb = (const u64*)x + (size_t)n*CIN*PCOLS;
#pragma unroll
    for (int j = 0; j < 8; j++) {    // 2048 u64, coalesced per warp
        int idx = t + 256*j;
        int c = idx >> 6, pcl = idx & 63;
        int pc = pc0 + pcl;
        Xs[c][pcl] = (pc < PCOLS) ? xb[(size_t)c*PCOLS + pc] : 0ull;
    }
    __syncthreads();

    int og = t >> 6, pcl = t & 63;
    int pc = pc0 + pcl;

    u64 acc[8];
#pragma unroll
    for (int j = 0; j < 8; j++) acc[j] = 0ull;
#pragma unroll
    for (int c = 0; c < CIN; c++) {
        u64 xv = Xs[c][pcl];
#pragma unroll
        for (int j = 0; j < 8; j++) ffma2(acc[j], Ws2[c][og*8 + j], xv);
    }
    if (pc >= PCOLS) return;
    u64* y2 = (u64*)g_Y + (size_t)n*COUT*PCOLS + (size_t)(og*8)*PCOLS + pc;
#pragma unroll
    for (int j = 0; j < 8; j++)
        y2[(size_t)j * PCOLS] = acc[j];
}

// ---- K2: node GEMM  out[n,o,v,l] = sum_w M[v,w] Y[n,o,w,l] + b[o] ------
// VT=64 (4 v-tiles -> low Y re-read), thread tile 8v x 3 cols (48 acc regs),
// register-prefetch of next chunk hides global latency across syncs.
#define VT 64
#define GP 16    // pairs per block (cols = 96 u64)
#define KC 16
#define YROW 98  // padded Ysh row (u64)
#define NCH 13   // ceil(207/16)
__global__ __launch_bounds__(256, 3) void k_node(const float* __restrict__ b,
                                                 float* __restrict__ out) {
    __shared__ u64 Ms2[VT][KC];      // 8 KB: M duplicated (m,m)
    __shared__ u64 Ysh[KC][YROW];    // 12.25 KB
    int v0  = blockIdx.x * VT;
    int pb  = blockIdx.y * GP;
    int tid = threadIdx.x;
    int ty  = tid >> 5, tx = tid & 31;   // ty: 8 v's each, tx: 3 cols

    u64 acc[8][3];
#pragma unroll
    for (int j = 0; j < 8; j++)
#pragma unroll
        for (int i = 0; i < 3; i++) acc[j][i] = 0ull;

    const u64*  yg = (const u64*)g_Y;
    const float* M = g_mats + 2*NSQ;
    u64* ysh = &Ysh[0][0];

    // Y staging plan: 1536 u64/chunk, 6 per thread, precomputed offsets
    u32 gofs[6], sofs[6];
    int kkj[6];
#pragma unroll
    for (int j = 0; j < 6; j++) {
        int i   = tid + 256*j;
        int p   = i / 96, r = i % 96;
        int kk  = r / 6,  pcz = r % 6;
        kkj[j]  = kk;
        gofs[j] = (u32)((pb + p)*PCOLS + kk*6 + pcz);
        sofs[j] = (u32)(kk*YROW + p*6 + pcz);
    }
    // M staging plan: VT*KC = 1024 elems, 4 per thread
    int mvl = tid >> 2;
    int mk  = (tid & 3) * 4;
    int mv  = v0 + mvl;

    // prefetch chunk 0
    u64 yreg[6]; float mreg[4];
#pragma unroll
    for (int j = 0; j < 6; j++) {
        yreg[j] = (kkj[j] < NNODES) ? yg[gofs[j]] : 0ull;
        gofs[j] += KC*6;
    }
#pragma unroll
    for (int jj = 0; jj < 4; jj++) {
        int w = mk + jj;
        mreg[jj] = (mv < NNODES && w < NNODES) ? M[mv*NNODES + w] : 0.f;
    }

    for (int ch = 0; ch < NCH; ch++) {
        // commit prefetched chunk to smem
#pragma unroll
        for (int j = 0; j < 6; j++) ysh[sofs[j]] = yreg[j];
#pragma unroll
        for (int jj = 0; jj < 4; jj++) Ms2[mvl][mk + jj] = pack2(mreg[jj]);
        __syncthreads();
        // prefetch next chunk (overlaps with compute below)
        if (ch + 1 < NCH) {
            int w0n = (ch + 1) * KC;
#pragma unroll
            for (int j = 0; j < 6; j++) {
                int w = w0n + kkj[j];
                yreg[j] = (w < NNODES) ? yg[gofs[j]] : 0ull;
                gofs[j] += KC*6;
            }
#pragma unroll
            for (int jj = 0; jj < 4; jj++) {
                int w = w0n + mk + jj;
                mreg[jj] = (mv < NNODES && w < NNODES) ? M[mv*NNODES + w] : 0.f;
            }
        }
        // compute
#pragma unroll
        for (int kk = 0; kk < KC; kk++) {
            u64 yv[3];
#pragma unroll
            for (int i = 0; i < 3; i++) yv[i] = Ysh[kk][tx + 32*i];
#pragma unroll
            for (int j = 0; j < 8; j++) {
                u64 m2 = Ms2[ty*8 + j][kk];
#pragma unroll
                for (int i = 0; i < 3; i++) ffma2(acc[j][i], m2, yv[i]);
            }
        }
        __syncthreads();
    }

    // epilogue: add bias, store packed (v,l) runs
    u64* o2 = (u64*)out;
#pragma unroll
    for (int i = 0; i < 3; i++) {
        int pcol = tx + 32*i;
        int p = pcol / 6, pcz = pcol % 6;
        int pair = pb + p;
        u64 b2 = pack2(b[pair & 31]);
#pragma unroll
        for (int j = 0; j < 8; j++) {
            int v = v0 + ty*8 + j;
            if (v < NNODES)
                o2[(size_t)pair*PCOLS + (size_t)v*6 + pcz] = add2(acc[j][i], b2);
        }
    }
}

extern "C" void kernel_launch(void* const* d_in, const int* in_sizes, int n_in,
                              void* d_out, int out_size) {
    const float* x   = (const float*)d_in[0];
    const float* adj = (const float*)d_in[1];
    const float* W   = (const float*)d_in[2];
    const float* b   = (const float*)d_in[3];
    float* out = (float*)d_out;

    k_norm<<<NNODES, 256>>>(adj);
    k_A2 <<<NNODES, 224>>>();
    k_M  <<<NNODES, 224>>>();
    k_cmix<<<dim3((PCOLS + PCB - 1)/PCB, BATCH), 256>>>(x, W);
    k_node<<<dim3((NNODES + VT - 1)/VT, NPAIR/GP), 256>>>(b, out);
}

// round 14
// speedup vs baseline: 1.1700x; 1.1700x over previous
#include <cuda_runtime.h>

// Problem dims
#define NNODES 207
#define LT     12
#define CIN    32
#define COUT   32
#define BATCH  256
#define NPAIR  (BATCH*COUT)        // 8192 (n,o) pairs
#define COLSF  (NNODES*LT)         // 2484 floats per (n,c) slice
#define PCOLS  (COLSF/2)           // 1242 float2 per slice
#define XELEMS (BATCH*CIN*COLSF)   // 20,348,928
#define NSQ    (NNODES*NNODES)

typedef unsigned long long u64;
typedef unsigned int u32;

// Scratch (static device globals — no allocation). 256B-aligned: cp.async
// 16B granules need >=16B alignment of base + offset.
__device__ __align__(256) float g_mats[2*NSQ];    // [0]=A, [1]=A2
__device__ __align__(256) u64   g_Mt[208*240];    // M^T [w][v], dup (m,m), 0-pad
__device__ __align__(256) float g_Y[XELEMS + 32]; // channel-mixed intermediate

// ---- packed fp32x2 helpers ---------------------------------------------
__device__ __forceinline__ u64 pack2(float x) {
    u64 r; asm("mov.b64 %0, {%1, %1};" : "=l"(r) : "f"(x)); return r;
}
__device__ __forceinline__ void ffma2(u64 &d, u64 a, u64 b) {
    asm("fma.rn.f32x2 %0, %1, %2, %0;" : "+l"(d) : "l"(a), "l"(b));
}
__device__ __forceinline__ u64 add2(u64 a, u64 b) {
    u64 r; asm("add.rn.f32x2 %0, %1, %2;" : "=l"(r) : "l"(a), "l"(b)); return r;
}
__device__ __forceinline__ void cpa16(u32 dst, const void* src) {
    asm volatile("cp.async.cg.shared.global [%0], [%1], 16;" :: "r"(dst), "l"(src));
}
__device__ __forceinline__ void cpa_commit() {
    asm volatile("cp.async.commit_group;");
}

// ---- K0a: row-normalized A = (adj + I) / rowsum ------------------------
__global__ void k_norm(const float* __restrict__ adj) {
    int v = blockIdx.x;
    __shared__ float red[256];
    float s = 0.f;
    for (int w = threadIdx.x; w < NNODES; w += 256)
        s += adj[v*NNODES + w] + (w == v ? 1.f : 0.f);
    red[threadIdx.x] = s;
    __syncthreads();
    for (int st = 128; st > 0; st >>= 1) {
        if (threadIdx.x < st) red[threadIdx.x] += red[threadIdx.x + st];
        __syncthreads();
    }
    float inv = 1.f / red[0];
    for (int w = threadIdx.x; w < NNODES; w += 256)
        g_mats[v*NNODES + w] = (adj[v*NNODES + w] + (w == v ? 1.f : 0.f)) * inv;
}

// ---- K0b: A2 = A @ A ---------------------------------------------------
__global__ void k_A2() {
    int v = blockIdx.x, u = threadIdx.x;
    if (u >= NNODES) return;
    const float* A = g_mats;
    float acc = 0.f;
    for (int w = 0; w < NNODES; w++)
        acc += A[v*NNODES + w] * A[w*NNODES + u];
    g_mats[NSQ + v*NNODES + u] = acc;
}

// ---- K0c: Mt[w][v] = dup( AL*I + c1*A + c2*A2 + c3*(A2@A) )[v][w] ------
__global__ void k_M() {
    const float AL = 0.05f, BE = 0.95f;
    const float c1 = AL*BE, c2 = AL*BE*BE, c3 = BE*BE*BE;
    int v = blockIdx.x, u = threadIdx.x;
    if (u >= NNODES) return;
    const float* A  = g_mats;
    const float* A2 = g_mats + NSQ;
    float acc = 0.f;
    for (int w = 0; w < NNODES; w++)
        acc += A2[v*NNODES + w] * A[w*NNODES + u];
    float r = c3*acc + c2*A2[v*NNODES + u] + c1*A[v*NNODES + u]
            + (u == v ? AL : 0.f);
    g_Mt[u*240 + v] = pack2(r);       // transposed; row 207 / cols>=207 stay 0
}

// ---- K1: channel mix  Y[n,o,w,l] = sum_c W[o,c] x[n,c,w,l] -------------
// W reads vectorized (LDS.128 broadcasts): 5 LDS per 8 FFMA2.
#define PCB 64   // packed columns per block
__global__ __launch_bounds__(256) void k_cmix(const float* __restrict__ x,
                                              const float* __restrict__ W,
                                              int n0) {
    __shared__ u64 Ws2[CIN][COUT];   // 8 KB: [c][o], duplicated halves
    __shared__ u64 Xs [CIN][PCB];    // 16 KB
    int n   = n0 + blockIdx.y;
    int t   = threadIdx.x;
    int pc0 = blockIdx.x * PCB;

    for (int i = t; i < CIN*COUT; i += 256) {
        int o = i >> 5, c = i & 31;
        Ws2[c][o] = pack2(W[i]);     // W layout (COUT, CIN)
    }
    const u64* xb = (const u64*)x + (size_t)n*CIN*PCOLS;
#pragma unroll
    for (int j = 0; j < 8; j++) {    // 2048 u64, coalesced per warp
        int idx = t + 256*j;
        int c = idx >> 6, pcl = idx & 63;
        int pc = pc0 + pcl;
        Xs[c][pcl] = (pc < PCOLS) ? xb[(size_t)c*PCOLS + pc] : 0ull;
    }
    __syncthreads();

    int og = t >> 6, pcl = t & 63;
    int pc = pc0 + pcl;

    u64 acc[8];
#pragma unroll
    for (int j = 0; j < 8; j++) acc[j] = 0ull;
#pragma unroll
    for (int c = 0; c < CIN; c++) {
        u64 xv = Xs[c][pcl];
        const ulonglong2* wr = (const ulonglong2*)&Ws2[c][og*8];
        ulonglong2 w01 = wr[0], w23 = wr[1], w45 = wr[2], w67 = wr[3];
        ffma2(acc[0], w01.x, xv); ffma2(acc[1], w01.y, xv);
        ffma2(acc[2], w23.x, xv); ffma2(acc[3], w23.y, xv);
        ffma2(acc[4], w45.x, xv); ffma2(acc[5], w45.y, xv);
        ffma2(acc[6], w67.x, xv); ffma2(acc[7], w67.y, xv);
    }
    if (pc >= PCOLS) return;
    u64* y2 = (u64*)g_Y + (size_t)n*COUT*PCOLS + (size_t)(og*8)*PCOLS + pc;
#pragma unroll
    for (int j = 0; j < 8; j++)
        y2[(size_t)j * PCOLS] = acc[j];
}

// ---- K2: node GEMM  out[n,o,v,l] = sum_w M[v,w] Y[n,o,w,l] + b[o] ------
// 6v x 6c tile; all smem reads LDS.128 (M reads are warp-broadcasts);
// cp.async double-buffered staging. 30 KB static smem, 2 CTAs/SM.
#define VT 48
#define GP 32     // pairs per block = one n, all 32 o
#define KC 8
#define CROW 192  // u64 cols per Ysh row
#define NCH 26    // ceil(207/8)
__global__ __launch_bounds__(256, 2) void k_node(const float* __restrict__ b,
                                                 float* __restrict__ out) {
    __shared__ u64 Ysh[2][KC][CROW];   // 2 x 12 KB
    __shared__ u64 Ms2[2][KC][VT];     // 2 x 3 KB, [kk][vl]
    int v0  = blockIdx.x * VT;         // 5 tiles: 0..192 (240 rows padded)
    int pb  = blockIdx.y * GP;
    int tid = threadIdx.x;
    int ty  = tid >> 5, tx = tid & 31;  // ty: 6 v's, tx: 3 col-pairs

    u64 acc[6][6];
#pragma unroll
    for (int j = 0; j < 6; j++)
#pragma unroll
        for (int i = 0; i < 6; i++) acc[j][i] = 0ull;

    const char* ygb = (const char*)g_Y;
    const char* mgb = (const char*)g_Mt;

    // Y staging plan: 768 16B-granules/chunk, 3/thread
    u32 ysrc[3], ydst[3];
#pragma unroll
    for (int j = 0; j < 3; j++) {
        int g  = tid + 256*j;
        int p  = g / 24, r = g % 24;
        int kk = r / 3, qz = (r % 3) * 2;
        ysrc[j] = (u32)(((pb + p)*PCOLS + kk*6 + qz) * 8);
        ydst[j] = (u32)((kk*CROW + p*6 + qz) * 8);
    }
    // M staging plan: 192 16B-granules/chunk, 1 for tid<192
    bool mdo = tid < 192;
    int  mkk = tid / 24;
    int  mvp = (tid % 24) * 2;
    u32  msrc = (u32)((mkk*240 + v0 + mvp) * 8);
    u32  mdst = (u32)((mkk*VT + mvp) * 8);

    u32 ysh0 = (u32)__cvta_generic_to_shared(&Ysh[0][0][0]);
    u32 msh0 = (u32)__cvta_generic_to_shared(&Ms2[0][0][0]);

    // stage chunk 0 -> buf 0
#pragma unroll
    for (int j = 0; j < 3; j++) cpa16(ysh0 + ydst[j], ygb + ysrc[j]);
    if (mdo) cpa16(msh0 + mdst, mgb + msrc);
    cpa_commit();

    for (int ch = 0; ch < NCH; ch++) {
        int buf = ch & 1;
        if (ch + 1 < NCH) {
            int nb = (ch + 1) & 1;
            u32 yofs = (u32)(nb * KC * CROW * 8);
            u32 mofs = (u32)(nb * KC * VT * 8);
#pragma unroll
            for (int j = 0; j < 3; j++) {
                ysrc[j] += KC*6*8;
                cpa16(ysh0 + yofs + ydst[j], ygb + ysrc[j]);
            }
            if (mdo) {
                msrc += KC*240*8;
                cpa16(msh0 + mofs + mdst, mgb + msrc);
            }
            cpa_commit();
            asm volatile("cp.async.wait_group 1;");
        } else {
            asm volatile("cp.async.wait_group 0;");
        }
        __syncthreads();

#pragma unroll
        for (int kk = 0; kk < KC; kk++) {
            const ulonglong2* mr = (const ulonglong2*)&Ms2[buf][kk][ty*6];
            ulonglong2 m01 = mr[0], m23 = mr[1], m45 = mr[2];
            ulonglong2 y0 = *(const ulonglong2*)&Ysh[buf][kk][2*tx];
            ulonglong2 y1 = *(const ulonglong2*)&Ysh[buf][kk][2*tx + 64];
            ulonglong2 y2 = *(const ulonglong2*)&Ysh[buf][kk][2*tx + 128];
            u64 mv[6] = {m01.x, m01.y, m23.x, m23.y, m45.x, m45.y};
            u64 yv[6] = {y0.x, y0.y, y1.x, y1.y, y2.x, y2.y};
#pragma unroll
            for (int j = 0; j < 6; j++)
#pragma unroll
                for (int i = 0; i < 6; i++)
                    ffma2(acc[j][i], mv[j], yv[i]);
        }
        __syncthreads();
    }

    // epilogue: add bias, store 16B per (v, col-pair)
    char* ob = (char*)out;
#pragma unroll
    for (int i = 0; i < 3; i++) {
        int c0 = 2*tx + 64*i;
        int p = c0 / 6, qz = c0 % 6;          // qz even; both cols same p
        int pair = pb + p;
        u64 b2 = pack2(b[pair & 31]);
#pragma unroll
        for (int j = 0; j < 6; j++) {
            int v = v0 + ty*6 + j;
            if (v < NNODES) {
                ulonglong2 st;
                st.x = add2(acc[j][2*i],     b2);
                st.y = add2(acc[j][2*i + 1], b2);
                *(ulonglong2*)(ob + ((size_t)pair*PCOLS + v*6 + qz)*8) = st;
            }
        }
    }
}

extern "C" void kernel_launch(void* const* d_in, const int* in_sizes, int n_in,
                              void* d_out, int out_size) {
    const float* x   = (const float*)d_in[0];
    const float* adj = (const float*)d_in[1];
    const float* W   = (const float*)d_in[2];
    const float* b   = (const float*)d_in[3];
    float* out = (float*)d_out;

    k_norm<<<NNODES, 256>>>(adj);
    k_A2 <<<NNODES, 224>>>();
    k_M  <<<NNODES, 224>>>();
    // split cmix so ncu's capture slot lands on k_node (launch #6)
    k_cmix<<<dim3((PCOLS + PCB - 1)/PCB, BATCH/2), 256>>>(x, W, 0);
    k_cmix<<<dim3((PCOLS + PCB - 1)/PCB, BATCH/2), 256>>>(x, W, BATCH/2);
    k_node<<<dim3((NNODES + VT - 1)/VT, NPAIR/GP), 256>>>(b, out);
}